// round 14
// baseline (speedup 1.0000x reference)
#include <cuda_runtime.h>
#include <math.h>
#include <stdint.h>

#define SS 1024
#define CS 768
#define CZ 128
#define NH 24
#define DD 32
#define NB 2
#define L2E 1.4426950408889634f

// ---- scratch ----
__device__ float    g_emb[NB * 3 * CS];
__device__ unsigned g_bsn[NB * SS * CS];                 // tf32 bits
__device__ unsigned g_qkv[3 * NB * NH * SS * DD];        // tf32 bits (q pre-scaled, rms folded)
__device__ float    g_bias[(size_t)NH * SS * SS];        // (h,i,j) fp32, z-part only
__device__ unsigned g_att[NB * SS * CS];                 // tf32 bits
__device__ unsigned g_w[4][CS * CS];                     // tf32 wq,wk,wv,wo
__device__ unsigned g_wtp[NH * CZ];                      // tf32 lnw*wz, [n][k]
__device__ float    g_ah[NH], g_bh[NH];

__device__ __forceinline__ unsigned f2tf(float x) {
    unsigned u; asm("cvt.rna.tf32.f32 %0, %1;" : "=r"(u) : "f"(x)); return u;
}
__device__ __forceinline__ void mma8(float* c, const unsigned* a, unsigned b0, unsigned b1) {
    asm volatile("mma.sync.aligned.m16n8k8.row.col.f32.tf32.tf32.f32 "
        "{%0,%1,%2,%3},{%4,%5,%6,%7},{%8,%9},{%0,%1,%2,%3};"
        : "+f"(c[0]), "+f"(c[1]), "+f"(c[2]), "+f"(c[3])
        : "r"(a[0]), "r"(a[1]), "r"(a[2]), "r"(a[3]), "r"(b0), "r"(b1));
}
__device__ __forceinline__ void cpa16(void* s, const void* g) {
    asm volatile("cp.async.cg.shared.global [%0], [%1], 16;"
                 :: "r"((unsigned)__cvta_generic_to_shared(s)), "l"(g));
}
__device__ __forceinline__ void cp_commit() { asm volatile("cp.async.commit_group;"); }
__device__ __forceinline__ void cp_wait0()  { asm volatile("cp.async.wait_group 0;"); }

// fast 2^y on fma pipe; caller clamps y >= -126
__device__ __forceinline__ float fexp2(float y) {
    float t = y + 12582912.f;
    int ei = __float_as_int(t) << 23;
    float f = y - (t - 12582912.f);
    float p = 0.0013333558f;
    p = fmaf(p, f, 0.0096181291f);
    p = fmaf(p, f, 0.0555041087f);
    p = fmaf(p, f, 0.2402265069f);
    p = fmaf(p, f, 0.6931471806f);
    p = fmaf(p, f, 1.f);
    return __int_as_float(__float_as_int(p) + ei);
}

// ============================================================
// 0a. weight pre-convert to tf32
// ============================================================
__global__ void wconv_kernel(const float* __restrict__ wq, const float* __restrict__ wk,
                             const float* __restrict__ wv, const float* __restrict__ wo) {
    int i4 = (blockIdx.x * 256 + threadIdx.x) * 4;
    if (i4 >= CS * CS) return;
    const float* src[4] = {wq, wk, wv, wo};
#pragma unroll
    for (int a = 0; a < 4; a++) {
        float4 v = *(const float4*)(src[a] + i4);
        uint4 u = {f2tf(v.x), f2tf(v.y), f2tf(v.z), f2tf(v.w)};
        *(uint4*)&g_w[a][i4] = u;
    }
}

// ============================================================
// 0b. bias prep: WT = tf32(lnw*wz) [n][k], Ah, Bh  (one block)
// ============================================================
__global__ void bprep_kernel(const float* __restrict__ lnw, const float* __restrict__ lnb,
                             const float* __restrict__ wz) {
    int tid = threadIdx.x;
    for (int idx = tid; idx < NH * CZ; idx += 256) {
        int n = idx >> 7, k = idx & 127;
        g_wtp[idx] = f2tf(lnw[k] * wz[k * NH + n]);
    }
    if (tid < NH) {
        float a = 0.f, bb = 0.f;
        for (int k = 0; k < CZ; k++) {
            float wv = wz[k * NH + tid];
            a += lnw[k] * wv; bb += lnb[k] * wv;
        }
        g_ah[tid] = a; g_bh[tid] = bb;
    }
}

// ============================================================
// 1. adaLN
// ============================================================
__global__ void adaln_kernel(const float* __restrict__ t,
                             const float* __restrict__ w,
                             const float* __restrict__ bb) {
    int b = blockIdx.y;
    int n = blockIdx.x * 256 + threadIdx.x;
    __shared__ float st[CS];
    for (int c = threadIdx.x; c < CS; c += 256) {
        float v = t[b * CS + c];
        st[c] = v / (1.f + __expf(-v));
    }
    __syncthreads();
    float acc = bb[n];
#pragma unroll 4
    for (int c = 0; c < CS; c++) acc = fmaf(st[c], w[c * (3 * CS) + n], acc);
    g_emb[b * 3 * CS + n] = acc;
}

// ============================================================
// 2. bs LayerNorm + adaLN modulate -> tf32 g_bsn
// ============================================================
__global__ void bsnorm_kernel(const float* __restrict__ bs) {
    int row = blockIdx.x;
    int b = row >> 10;
    const float* x = bs + (size_t)row * CS;
    int tid = threadIdx.x;
    float v0 = x[tid], v1 = x[tid + 256], v2 = x[tid + 512];

    __shared__ float red1[8], red2[8];
    float s = v0 + v1 + v2;
    for (int o = 16; o; o >>= 1) s += __shfl_xor_sync(~0u, s, o);
    if ((tid & 31) == 0) red1[tid >> 5] = s;
    __syncthreads();
    float tot = 0.f;
#pragma unroll
    for (int i = 0; i < 8; i++) tot += red1[i];
    float mu = tot * (1.f / CS);

    float d0 = v0 - mu, d1 = v1 - mu, d2 = v2 - mu;
    float q = d0 * d0 + d1 * d1 + d2 * d2;
    for (int o = 16; o; o >>= 1) q += __shfl_xor_sync(~0u, q, o);
    if ((tid & 31) == 0) red2[tid >> 5] = q;
    __syncthreads();
    float tot2 = 0.f;
#pragma unroll
    for (int i = 0; i < 8; i++) tot2 += red2[i];
    float rsig = rsqrtf(tot2 * (1.f / CS) + 1e-5f);

    const float* e = g_emb + b * 3 * CS;
    unsigned* outp = g_bsn + (size_t)row * CS;
    outp[tid]       = f2tf(d0 * rsig * (1.f + e[CS + tid])       + e[tid]);
    outp[tid + 256] = f2tf(d1 * rsig * (1.f + e[CS + tid + 256]) + e[tid + 256]);
    outp[tid + 512] = f2tf(d2 * rsig * (1.f + e[CS + tid + 512]) + e[tid + 512]);
}

// ============================================================
// 3. QKV GEMM, cp.async double-buffered, fused RMS + q-scale
// ============================================================
__global__ __launch_bounds__(256) void qkv_mma2(const float* __restrict__ rqw,
                                                const float* __restrict__ rkw) {
    __shared__ unsigned As[2][128][20];
    __shared__ unsigned Bs[2][16][136];
    int tid = threadIdx.x, w = tid >> 5, lane = tid & 31, g = lane >> 2, c = lane & 3;
    int wm = w & 3, wn = w >> 2;
    int n0 = blockIdx.x * 128;
    int sel = n0 / CS, nc = n0 - sel * CS;
    const unsigned* W = g_w[sel];
    int m0 = blockIdx.y * 128;

    float acc0[8][4] = {}, acc1[8][4] = {};
#pragma unroll
    for (int i = 0; i < 2; i++) {
        int ch = tid * 2 + i;
        int ar = ch >> 2, ac = (ch & 3) * 4;
        cpa16(&As[0][ar][ac], g_bsn + (size_t)(m0 + ar) * CS + ac);
        int br = ch >> 5, bc = (ch & 31) * 4;
        cpa16(&Bs[0][br][bc], W + (size_t)br * CS + nc + bc);
    }
    cp_commit(); cp_wait0();
    __syncthreads();

    int buf = 0;
    for (int it = 0; it < 48; it++) {
        if (it < 47) {
            int kn = (it + 1) * 16;
#pragma unroll
            for (int i = 0; i < 2; i++) {
                int ch = tid * 2 + i;
                int ar = ch >> 2, ac = (ch & 3) * 4;
                cpa16(&As[buf ^ 1][ar][ac], g_bsn + (size_t)(m0 + ar) * CS + kn + ac);
                int br = ch >> 5, bc = (ch & 31) * 4;
                cpa16(&Bs[buf ^ 1][br][bc], W + (size_t)(kn + br) * CS + nc + bc);
            }
            cp_commit();
        }
#pragma unroll
        for (int ks = 0; ks < 2; ks++) {
            int r0 = wm * 32 + g;
            unsigned a0[4] = {As[buf][r0][8 * ks + c], As[buf][r0 + 8][8 * ks + c],
                              As[buf][r0][8 * ks + c + 4], As[buf][r0 + 8][8 * ks + c + 4]};
            unsigned a1[4] = {As[buf][r0 + 16][8 * ks + c], As[buf][r0 + 24][8 * ks + c],
                              As[buf][r0 + 16][8 * ks + c + 4], As[buf][r0 + 24][8 * ks + c + 4]};
#pragma unroll
            for (int nt = 0; nt < 8; nt++) {
                unsigned b0 = Bs[buf][8 * ks + c][wn * 64 + 8 * nt + g];
                unsigned b1 = Bs[buf][8 * ks + c + 4][wn * 64 + 8 * nt + g];
                mma8(acc0[nt], a0, b0, b1);
                mma8(acc1[nt], a1, b0, b1);
            }
        }
        if (it < 47) {
            cp_wait0();
            __syncthreads();
            buf ^= 1;
        }
    }

    const float SC = 0.17677669529663687f;
    int bi = m0 >> 10;
    int r0g = m0 + wm * 32 + g;
#pragma unroll
    for (int mi = 0; mi < 2; mi++) {
        float (*ac)[4] = mi ? acc1 : acc0;
        int rb = r0g + mi * 16;
        int s0 = rb & 1023, s1 = s0 + 8;
#pragma unroll
        for (int hf = 0; hf < 2; hf++) {
            int h = (nc + wn * 64 + hf * 32) >> 5;
            float ss0 = 0.f, ss1 = 0.f;
#pragma unroll
            for (int nt = hf * 4; nt < hf * 4 + 4; nt++) {
                ss0 += ac[nt][0] * ac[nt][0] + ac[nt][1] * ac[nt][1];
                ss1 += ac[nt][2] * ac[nt][2] + ac[nt][3] * ac[nt][3];
            }
            float rs0 = 1.f, rs1 = 1.f;
            if (sel < 2) {
                ss0 += __shfl_xor_sync(~0u, ss0, 1); ss0 += __shfl_xor_sync(~0u, ss0, 2);
                ss1 += __shfl_xor_sync(~0u, ss1, 1); ss1 += __shfl_xor_sync(~0u, ss1, 2);
                rs0 = rsqrtf(ss0 * (1.f / 32) + 1e-5f);
                rs1 = rsqrtf(ss1 * (1.f / 32) + 1e-5f);
                if (sel == 0) { rs0 *= SC; rs1 *= SC; }
            }
            unsigned* basep = g_qkv + ((size_t)(sel * NB + bi) * NH + h) * SS * DD;
            const float* wr = (sel == 0) ? rqw : rkw;
#pragma unroll
            for (int nt = hf * 4; nt < hf * 4 + 4; nt++) {
                int d = (8 * nt + 2 * c) & 31;
                float w0 = 1.f, w1 = 1.f;
                if (sel < 2) { w0 = wr[d]; w1 = wr[d + 1]; }
                unsigned* p0 = basep + (size_t)s0 * DD + d;
                p0[0] = f2tf(ac[nt][0] * rs0 * w0); p0[1] = f2tf(ac[nt][1] * rs0 * w1);
                unsigned* p1 = basep + (size_t)s1 * DD + d;
                p1[0] = f2tf(ac[nt][2] * rs1 * w0); p1[1] = f2tf(ac[nt][3] * rs1 * w1);
            }
        }
    }
}

// ============================================================
// 4. bias via tf32 mma (R11 form: unconditional coalesced
//    cp.async staging issued at cycle 0), (h,i,j) output
// ============================================================
struct BiasSmem {
    unsigned Zs[128][132];
    unsigned WT[24][132];        // WT for mma; reused as float Out[24][132] in epilogue
    float muS[128], rsS[128];
    float AhS[24], BhS[24];
    int mS[128];
};

__global__ __launch_bounds__(256) void bias_mma2(const float* __restrict__ z,
                                                 const int* __restrict__ zmask) {
    extern __shared__ char smem_raw[];
    BiasSmem* sm = (BiasSmem*)smem_raw;
    int i = blockIdx.y, jt = blockIdx.x * 128;
    int tid = threadIdx.x, w = tid >> 5, lane = tid & 31, g = lane >> 2, c = lane & 3;

    // coalesced z staging first (issues immediately): lane l covers bytes [16l,16l+16)
    const float* zbase = z + ((size_t)i * SS + jt) * CZ;
#pragma unroll
    for (int it = 0; it < 16; it++) {
        int ch = tid + 256 * it;
        int r = ch >> 5, col = (ch & 31) * 4;
        cpa16(&sm->Zs[r][col], zbase + (size_t)r * CZ + col);
    }
    cp_commit();

    for (int idx = tid; idx < NH * CZ; idx += 256) {
        int n = idx >> 7, k = idx & 127;
        sm->WT[n][k] = g_wtp[idx];
    }
    if (tid < NH) { sm->AhS[tid] = g_ah[tid]; sm->BhS[tid] = g_bh[tid]; }
    if (tid < 128) sm->mS[tid] = zmask[(size_t)i * SS + jt + tid];
    cp_wait0();
    __syncthreads();

    // LN stats from smem
    {
        int r = tid >> 1, hh = tid & 1;
        const float4* zr = (const float4*)&sm->Zs[r][hh * 64];
        float s = 0.f, q = 0.f;
#pragma unroll
        for (int t = 0; t < 16; t++) {
            float4 v = zr[t];
            s += v.x + v.y + v.z + v.w;
            q += v.x * v.x + v.y * v.y + v.z * v.z + v.w * v.w;
        }
        s += __shfl_xor_sync(~0u, s, 1);
        q += __shfl_xor_sync(~0u, q, 1);
        if (hh == 0) {
            float mu = s * (1.f / CZ);
            float var = q * (1.f / CZ) - mu * mu;
            sm->muS[r] = mu;
            sm->rsS[r] = rsqrtf(var + 1e-5f);
        }
    }
    __syncthreads();

    float acc[3][4] = {};
#pragma unroll
    for (int ks = 0; ks < 16; ks++) {
        unsigned a[4] = {sm->Zs[16 * w + g][8 * ks + c], sm->Zs[16 * w + g + 8][8 * ks + c],
                         sm->Zs[16 * w + g][8 * ks + c + 4], sm->Zs[16 * w + g + 8][8 * ks + c + 4]};
#pragma unroll
        for (int nt = 0; nt < 3; nt++)
            mma8(acc[nt], a, sm->WT[8 * nt + g][8 * ks + c], sm->WT[8 * nt + g][8 * ks + c + 4]);
    }

    int j0 = 16 * w + g, j1 = j0 + 8;
    float mu0 = sm->muS[j0], rg0 = sm->rsS[j0], mu1 = sm->muS[j1], rg1 = sm->rsS[j1];
    bool k0m = sm->mS[j0] != 0, k1m = sm->mS[j1] != 0;

    __syncthreads();                       // all mma WT reads done; reuse as Out
    float* Ot = (float*)&sm->WT[0][0];     // [24][132]
#pragma unroll
    for (int nt = 0; nt < 3; nt++) {
        int h = 8 * nt + 2 * c;
        float A0 = sm->AhS[h], B0 = sm->BhS[h], A1 = sm->AhS[h + 1], B1 = sm->BhS[h + 1];
        Ot[h * 132 + j0]       = k0m ? rg0 * (acc[nt][0] - mu0 * A0) + B0 : -1e9f;
        Ot[(h + 1) * 132 + j0] = k0m ? rg0 * (acc[nt][1] - mu0 * A1) + B1 : -1e9f;
        Ot[h * 132 + j1]       = k1m ? rg1 * (acc[nt][2] - mu1 * A0) + B0 : -1e9f;
        Ot[(h + 1) * 132 + j1] = k1m ? rg1 * (acc[nt][3] - mu1 * A1) + B1 : -1e9f;
    }
    __syncthreads();

    // coalesced write: (h,i,j)
    for (int idx = tid; idx < 24 * 32; idx += 256) {
        int hh = idx >> 5, j4 = (idx & 31) * 4;
        float4 v = *(float4*)&Ot[hh * 132 + j4];
        *(float4*)(g_bias + ((size_t)hh * SS + i) * SS + jt + j4) = v;
    }
}

// ============================================================
// 5. flash attention: FIXED-MAX softmax (scores provably < 8;
//    M=16 const) — no running max, no rescale; q-tile 64,
//    128 thr, 4 CTA/SM; two-stream bias (zbias + L2-hot beta)
// ============================================================
#define MFIX (16.f * L2E)

struct AttnSmem {
    unsigned Ks[2][64][36];
    unsigned Vs[2][64][40];
    float    Ps[64][68];    // Q staging, then P
};

__global__ __launch_bounds__(128, 4) void attn_mma(const float* __restrict__ beta) {
    extern __shared__ char smem_raw[];
    AttnSmem* sm = (AttnSmem*)smem_raw;
    int b = blockIdx.z, h = blockIdx.y, q0 = blockIdx.x * 64;
    int tid = threadIdx.x, w = tid >> 5, lane = tid & 31, g = lane >> 2, c = lane & 3;

    const unsigned* qptr = g_qkv + ((size_t)(0 * NB + b) * NH + h) * SS * DD;
    const unsigned* kptr = g_qkv + ((size_t)(1 * NB + b) * NH + h) * SS * DD;
    const unsigned* vptr = g_qkv + ((size_t)(2 * NB + b) * NH + h) * SS * DD;
    const float* zbp = g_bias + ((size_t)h * SS + q0) * SS;
    const float* btp = beta + ((size_t)b * SS + q0) * SS;

    // stage Q (64x32) into Ps region + K/V tile 0
#pragma unroll
    for (int i = 0; i < 4; i++) {
        int ch = tid + 128 * i;
        int r = ch >> 3, col = (ch & 7) * 4;
        cpa16(&sm->Ps[r][col], qptr + (size_t)(q0 + r) * DD + col);
    }
#pragma unroll
    for (int i = 0; i < 4; i++) {
        int ch = tid + 128 * i;
        int r = ch >> 3, col = (ch & 7) * 4;
        cpa16(&sm->Ks[0][r][col], kptr + (size_t)r * DD + col);
        cpa16(&sm->Vs[0][r][col], vptr + (size_t)r * DD + col);
    }
    cp_commit(); cp_wait0();
    __syncthreads();

    unsigned qa[4][4];
#pragma unroll
    for (int ks = 0; ks < 4; ks++) {
        qa[ks][0] = __float_as_uint(sm->Ps[16 * w + g][8 * ks + c]);
        qa[ks][1] = __float_as_uint(sm->Ps[16 * w + g + 8][8 * ks + c]);
        qa[ks][2] = __float_as_uint(sm->Ps[16 * w + g][8 * ks + c + 4]);
        qa[ks][3] = __float_as_uint(sm->Ps[16 * w + g + 8][8 * ks + c + 4]);
    }
    // Ps rows [16w+g, 16w+g+8] are read/written ONLY by warp w

    float l0 = 0.f, l1 = 0.f;
    float o[4][4] = {};

    int buf = 0;
    for (int kt = 0; kt < 16; kt++) {
        int k0 = kt * 64;
        if (kt < 15) {
            int kn = k0 + 64;
#pragma unroll
            for (int i = 0; i < 4; i++) {
                int ch = tid + 128 * i;
                int r = ch >> 3, col = (ch & 7) * 4;
                cpa16(&sm->Ks[buf ^ 1][r][col], kptr + (size_t)(kn + r) * DD + col);
                cpa16(&sm->Vs[buf ^ 1][r][col], vptr + (size_t)(kn + r) * DD + col);
            }
            cp_commit();
        }

        float s[8][4] = {};
#pragma unroll
        for (int ks = 0; ks < 4; ks++) {
#pragma unroll
            for (int nt = 0; nt < 8; nt++)
                mma8(s[nt], qa[ks], sm->Ks[buf][8 * nt + g][8 * ks + c],
                                    sm->Ks[buf][8 * nt + g][8 * ks + c + 4]);
        }
        // bias add + fixed-max exp, single fused pass
        const float* z0 = zbp + (size_t)(16 * w + g) * SS + k0 + 2 * c;
        const float* z1 = z0 + 8 * SS;
        const float* t0 = btp + (size_t)(16 * w + g) * SS + k0 + 2 * c;
        const float* t1 = t0 + 8 * SS;
        float rs0 = 0.f, rs1 = 0.f;
#pragma unroll
        for (int nt = 0; nt < 8; nt++) {
            float2 za = *(const float2*)(z0 + 8 * nt);
            float2 zc = *(const float2*)(z1 + 8 * nt);
            float2 ba = *(const float2*)(t0 + 8 * nt);
            float2 bc = *(const float2*)(t1 + 8 * nt);
            float e0 = fexp2(fmaxf(fmaf(s[nt][0] + za.x + ba.x, L2E, -MFIX), -126.f));
            float e1 = fexp2(fmaxf(fmaf(s[nt][1] + za.y + ba.y, L2E, -MFIX), -126.f));
            float e2 = fexp2(fmaxf(fmaf(s[nt][2] + zc.x + bc.x, L2E, -MFIX), -126.f));
            float e3 = fexp2(fmaxf(fmaf(s[nt][3] + zc.y + bc.y, L2E, -MFIX), -126.f));
            rs0 += e0 + e1; rs1 += e2 + e3;
            float2 f0 = {e0, e1};
            *(float2*)&sm->Ps[16 * w + g][8 * nt + 2 * c] = f0;
            float2 f1 = {e2, e3};
            *(float2*)&sm->Ps[16 * w + g + 8][8 * nt + 2 * c] = f1;
        }
        l0 += rs0; l1 += rs1;
        __syncwarp();
#pragma unroll
        for (int ks = 0; ks < 8; ks++) {
            unsigned pa[4] = {__float_as_uint(sm->Ps[16 * w + g][8 * ks + c]),
                              __float_as_uint(sm->Ps[16 * w + g + 8][8 * ks + c]),
                              __float_as_uint(sm->Ps[16 * w + g][8 * ks + c + 4]),
                              __float_as_uint(sm->Ps[16 * w + g + 8][8 * ks + c + 4])};
#pragma unroll
            for (int nt = 0; nt < 4; nt++)
                mma8(o[nt], pa, sm->Vs[buf][8 * ks + c][8 * nt + g],
                                sm->Vs[buf][8 * ks + c + 4][8 * nt + g]);
        }
        if (kt < 15) cp_wait0();
        __syncthreads();
        buf ^= 1;
    }
    // row sums: lanes c=0..3 hold partial sums over their 2-col slices
    l0 += __shfl_xor_sync(~0u, l0, 1); l0 += __shfl_xor_sync(~0u, l0, 2);
    l1 += __shfl_xor_sync(~0u, l1, 1); l1 += __shfl_xor_sync(~0u, l1, 2);
    float inv0 = 1.f / l0, inv1 = 1.f / l1;
    int r0 = q0 + 16 * w + g, r1 = r0 + 8;
#pragma unroll
    for (int nt = 0; nt < 4; nt++) {
        int col = h * DD + 8 * nt + 2 * c;
        uint2 v0 = {f2tf(o[nt][0] * inv0), f2tf(o[nt][1] * inv0)};
        *(uint2*)(g_att + ((size_t)(b * SS + r0)) * CS + col) = v0;
        uint2 v1 = {f2tf(o[nt][2] * inv1), f2tf(o[nt][3] * inv1)};
        *(uint2*)(g_att + ((size_t)(b * SS + r1)) * CS + col) = v1;
    }
}

// ============================================================
// 6. out proj: cp.async double-buffered
// ============================================================
__global__ __launch_bounds__(256) void proj_mma2(const float* __restrict__ b_o,
                                                 float* __restrict__ out) {
    __shared__ unsigned As[2][128][20];
    __shared__ unsigned Bs[2][16][136];
    int tid = threadIdx.x, w = tid >> 5, lane = tid & 31, g = lane >> 2, c = lane & 3;
    int wm = w & 3, wn = w >> 2;
    int n0 = blockIdx.x * 128, m0 = blockIdx.y * 128;
    const unsigned* W = g_w[3];

    float acc0[8][4] = {}, acc1[8][4] = {};
#pragma unroll
    for (int i = 0; i < 2; i++) {
        int ch = tid * 2 + i;
        int ar = ch >> 2, ac = (ch & 3) * 4;
        cpa16(&As[0][ar][ac], g_att + (size_t)(m0 + ar) * CS + ac);
        int br = ch >> 5, bc = (ch & 31) * 4;
        cpa16(&Bs[0][br][bc], W + (size_t)br * CS + n0 + bc);
    }
    cp_commit(); cp_wait0();
    __syncthreads();

    int buf = 0;
    for (int it = 0; it < 48; it++) {
        if (it < 47) {
            int kn = (it + 1) * 16;
#pragma unroll
            for (int i = 0; i < 2; i++) {
                int ch = tid * 2 + i;
                int ar = ch >> 2, ac = (ch & 3) * 4;
                cpa16(&As[buf ^ 1][ar][ac], g_att + (size_t)(m0 + ar) * CS + kn + ac);
                int br = ch >> 5, bc = (ch & 31) * 4;
                cpa16(&Bs[buf ^ 1][br][bc], W + (size_t)(kn + br) * CS + n0 + bc);
            }
            cp_commit();
        }
#pragma unroll
        for (int ks = 0; ks < 2; ks++) {
            int r0 = wm * 32 + g;
            unsigned a0[4] = {As[buf][r0][8 * ks + c], As[buf][r0 + 8][8 * ks + c],
                              As[buf][r0][8 * ks + c + 4], As[buf][r0 + 8][8 * ks + c + 4]};
            unsigned a1[4] = {As[buf][r0 + 16][8 * ks + c], As[buf][r0 + 24][8 * ks + c],
                              As[buf][r0 + 16][8 * ks + c + 4], As[buf][r0 + 24][8 * ks + c + 4]};
#pragma unroll
            for (int nt = 0; nt < 8; nt++) {
                unsigned b0 = Bs[buf][8 * ks + c][wn * 64 + 8 * nt + g];
                unsigned b1 = Bs[buf][8 * ks + c + 4][wn * 64 + 8 * nt + g];
                mma8(acc0[nt], a0, b0, b1);
                mma8(acc1[nt], a1, b0, b1);
            }
        }
        if (it < 47) {
            cp_wait0();
            __syncthreads();
            buf ^= 1;
        }
    }

    int bi = m0 >> 10;
    const float* gate = g_emb + bi * 3 * CS + 2 * CS;
    int r0g = m0 + wm * 32 + g;
#pragma unroll
    for (int mi = 0; mi < 2; mi++) {
        float (*ac)[4] = mi ? acc1 : acc0;
        int rb = r0g + mi * 16;
#pragma unroll
        for (int nt = 0; nt < 8; nt++) {
            int col = n0 + wn * 64 + 8 * nt + 2 * c;
            float g0 = gate[col], g1 = gate[col + 1];
            float bo0 = b_o[col], bo1 = b_o[col + 1];
            float2 v0 = {(ac[nt][0] + bo0) * g0, (ac[nt][1] + bo1) * g1};
            *(float2*)(out + (size_t)rb * CS + col) = v0;
            float2 v1 = {(ac[nt][2] + bo0) * g0, (ac[nt][3] + bo1) * g1};
            *(float2*)(out + (size_t)(rb + 8) * CS + col) = v1;
        }
    }
}

// ============================================================
extern "C" void kernel_launch(void* const* d_in, const int* in_sizes, int n_in,
                              void* d_out, int out_size) {
    const float* bs      = (const float*)d_in[0];
    const float* z       = (const float*)d_in[1];
    const float* t       = (const float*)d_in[2];
    const float* beta    = (const float*)d_in[3];
    const int*   z_mask  = (const int*)  d_in[4];
    const float* w_adaln = (const float*)d_in[5];
    const float* b_adaln = (const float*)d_in[6];
    const float* ln_z_w  = (const float*)d_in[7];
    const float* ln_z_b  = (const float*)d_in[8];
    const float* w_q     = (const float*)d_in[9];
    const float* w_k     = (const float*)d_in[10];
    const float* w_v     = (const float*)d_in[11];
    const float* w_z     = (const float*)d_in[12];
    const float* rms_q_w = (const float*)d_in[13];
    const float* rms_k_w = (const float*)d_in[14];
    const float* w_o     = (const float*)d_in[15];
    const float* b_o     = (const float*)d_in[16];
    float* out = (float*)d_out;

    static const int ATTN_SMEM = (int)sizeof(AttnSmem);
    static const int BIAS_SMEM = (int)sizeof(BiasSmem);
    cudaFuncSetAttribute(attn_mma, cudaFuncAttributeMaxDynamicSharedMemorySize, ATTN_SMEM);
    cudaFuncSetAttribute(bias_mma2, cudaFuncAttributeMaxDynamicSharedMemorySize, BIAS_SMEM);

    adaln_kernel<<<dim3(9, 2), 256>>>(t, w_adaln, b_adaln);
    wconv_kernel<<<576, 256>>>(w_q, w_k, w_v, w_o);
    bprep_kernel<<<1, 256>>>(ln_z_w, ln_z_b, w_z);
    bsnorm_kernel<<<NB * SS, 256>>>(bs);
    bias_mma2<<<dim3(8, SS), 256, BIAS_SMEM>>>(z, z_mask);
    qkv_mma2<<<dim3(18, 16), 256>>>(rms_q_w, rms_k_w);
    attn_mma<<<dim3(16, NH, NB), 128, ATTN_SMEM>>>(beta);
    proj_mma2<<<dim3(6, 16), 256>>>(b_o, out);
}

// round 15
// speedup vs baseline: 1.2947x; 1.2947x over previous
#include <cuda_runtime.h>
#include <cuda_fp16.h>
#include <math.h>
#include <stdint.h>

#define SS 1024
#define CS 768
#define CZ 128
#define NH 24
#define DD 32
#define NB 2
#define L2E 1.4426950408889634f

// ---- scratch ----
__device__ float    g_emb[NB * 3 * CS];
__device__ __half   g_bsnh[NB * SS * CS];                // fp16
__device__ __half   g_qkvh[3 * NB * NH * SS * DD];       // fp16; q,k: (t,b,h,s,d); V: (b,h,d,s)
__device__ float    g_bias[(size_t)NH * SS * SS];        // (h,i,j) fp32, z-part only
__device__ __half   g_atth[NB * SS * CS];                // fp16
__device__ __half   g_wh[4][CS * CS];                    // fp16 TRANSPOSED [n][k]: wq,wk,wv,wo
__device__ unsigned g_wtp[NH * CZ];                      // tf32 lnw*wz, [n][k]
__device__ float    g_ah[NH], g_bh[NH];

__device__ __forceinline__ unsigned f2tf(float x) {
    unsigned u; asm("cvt.rna.tf32.f32 %0, %1;" : "=r"(u) : "f"(x)); return u;
}
// tf32 m16n8k8 (bias kernel only)
__device__ __forceinline__ void mma8(float* c, const unsigned* a, unsigned b0, unsigned b1) {
    asm volatile("mma.sync.aligned.m16n8k8.row.col.f32.tf32.tf32.f32 "
        "{%0,%1,%2,%3},{%4,%5,%6,%7},{%8,%9},{%0,%1,%2,%3};"
        : "+f"(c[0]), "+f"(c[1]), "+f"(c[2]), "+f"(c[3])
        : "r"(a[0]), "r"(a[1]), "r"(a[2]), "r"(a[3]), "r"(b0), "r"(b1));
}
// fp16 m16n8k16 (a,b half2-packed along k; fp32 accum)
__device__ __forceinline__ void mma16(float* c, const unsigned* a, unsigned b0, unsigned b1) {
    asm volatile("mma.sync.aligned.m16n8k16.row.col.f32.f16.f16.f32 "
        "{%0,%1,%2,%3},{%4,%5,%6,%7},{%8,%9},{%0,%1,%2,%3};"
        : "+f"(c[0]), "+f"(c[1]), "+f"(c[2]), "+f"(c[3])
        : "r"(a[0]), "r"(a[1]), "r"(a[2]), "r"(a[3]), "r"(b0), "r"(b1));
}
__device__ __forceinline__ void cpa16(void* s, const void* g) {
    asm volatile("cp.async.cg.shared.global [%0], [%1], 16;"
                 :: "r"((unsigned)__cvta_generic_to_shared(s)), "l"(g));
}
__device__ __forceinline__ void cp_commit() { asm volatile("cp.async.commit_group;"); }
__device__ __forceinline__ void cp_wait0()  { asm volatile("cp.async.wait_group 0;"); }

__device__ __forceinline__ float fexp2(float y) {
    float t = y + 12582912.f;
    int ei = __float_as_int(t) << 23;
    float f = y - (t - 12582912.f);
    float p = 0.0013333558f;
    p = fmaf(p, f, 0.0096181291f);
    p = fmaf(p, f, 0.0555041087f);
    p = fmaf(p, f, 0.2402265069f);
    p = fmaf(p, f, 0.6931471806f);
    p = fmaf(p, f, 1.f);
    return __int_as_float(__float_as_int(p) + ei);
}
__device__ __forceinline__ unsigned pack_h2(float a, float b) {
    __half2 h = __floats2half2_rn(a, b);
    return *(unsigned*)&h;
}

// ============================================================
// 0a. weight transpose+convert: g_wh[a][n][k] = fp16(w[k][n])
//     tiled 64x64 smem transpose
// ============================================================
__global__ void wconv_kernel(const float* __restrict__ wq, const float* __restrict__ wk,
                             const float* __restrict__ wv, const float* __restrict__ wo) {
    __shared__ float T[64][68];
    int a = blockIdx.z;
    const float* src[4] = {wq, wk, wv, wo};
    const float* W = src[a];
    int k0 = blockIdx.x * 64, n0 = blockIdx.y * 64;
    int tid = threadIdx.x;
#pragma unroll
    for (int i = 0; i < 4; i++) {
        int ch = tid + 256 * i;                 // 0..1023
        int r = ch >> 4, cc = (ch & 15) * 4;
        float4 v = *(const float4*)(W + (size_t)(k0 + r) * CS + n0 + cc);
        T[r][cc] = v.x; T[r][cc + 1] = v.y; T[r][cc + 2] = v.z; T[r][cc + 3] = v.w;
    }
    __syncthreads();
    int rn = tid >> 2, kc = (tid & 3) * 16;
    unsigned* dst = (unsigned*)(g_wh[a] + (size_t)(n0 + rn) * CS + k0 + kc);
#pragma unroll
    for (int j = 0; j < 8; j++)
        dst[j] = pack_h2(T[kc + 2 * j][rn], T[kc + 2 * j + 1][rn]);
}

// ============================================================
// 0b. bias prep (tf32, unchanged)
// ============================================================
__global__ void bprep_kernel(const float* __restrict__ lnw, const float* __restrict__ lnb,
                             const float* __restrict__ wz) {
    int tid = threadIdx.x;
    for (int idx = tid; idx < NH * CZ; idx += 256) {
        int n = idx >> 7, k = idx & 127;
        g_wtp[idx] = f2tf(lnw[k] * wz[k * NH + n]);
    }
    if (tid < NH) {
        float a = 0.f, bb = 0.f;
        for (int k = 0; k < CZ; k++) {
            float wv = wz[k * NH + tid];
            a += lnw[k] * wv; bb += lnb[k] * wv;
        }
        g_ah[tid] = a; g_bh[tid] = bb;
    }
}

// ============================================================
// 1. adaLN
// ============================================================
__global__ void adaln_kernel(const float* __restrict__ t,
                             const float* __restrict__ w,
                             const float* __restrict__ bb) {
    int b = blockIdx.y;
    int n = blockIdx.x * 256 + threadIdx.x;
    __shared__ float st[CS];
    for (int c = threadIdx.x; c < CS; c += 256) {
        float v = t[b * CS + c];
        st[c] = v / (1.f + __expf(-v));
    }
    __syncthreads();
    float acc = bb[n];
#pragma unroll 4
    for (int c = 0; c < CS; c++) acc = fmaf(st[c], w[c * (3 * CS) + n], acc);
    g_emb[b * 3 * CS + n] = acc;
}

// ============================================================
// 2. bs LayerNorm + adaLN modulate -> fp16 g_bsnh
// ============================================================
__global__ void bsnorm_kernel(const float* __restrict__ bs) {
    int row = blockIdx.x;
    int b = row >> 10;
    const float* x = bs + (size_t)row * CS;
    int tid = threadIdx.x;
    float v0 = x[tid], v1 = x[tid + 256], v2 = x[tid + 512];

    __shared__ float red1[8], red2[8];
    float s = v0 + v1 + v2;
    for (int o = 16; o; o >>= 1) s += __shfl_xor_sync(~0u, s, o);
    if ((tid & 31) == 0) red1[tid >> 5] = s;
    __syncthreads();
    float tot = 0.f;
#pragma unroll
    for (int i = 0; i < 8; i++) tot += red1[i];
    float mu = tot * (1.f / CS);

    float d0 = v0 - mu, d1 = v1 - mu, d2 = v2 - mu;
    float q = d0 * d0 + d1 * d1 + d2 * d2;
    for (int o = 16; o; o >>= 1) q += __shfl_xor_sync(~0u, q, o);
    if ((tid & 31) == 0) red2[tid >> 5] = q;
    __syncthreads();
    float tot2 = 0.f;
#pragma unroll
    for (int i = 0; i < 8; i++) tot2 += red2[i];
    float rsig = rsqrtf(tot2 * (1.f / CS) + 1e-5f);

    const float* e = g_emb + b * 3 * CS;
    __half* outp = g_bsnh + (size_t)row * CS;
    outp[tid]       = __float2half_rn(d0 * rsig * (1.f + e[CS + tid])       + e[tid]);
    outp[tid + 256] = __float2half_rn(d1 * rsig * (1.f + e[CS + tid + 256]) + e[tid + 256]);
    outp[tid + 512] = __float2half_rn(d2 * rsig * (1.f + e[CS + tid + 512]) + e[tid + 512]);
}

// ============================================================
// 3. QKV GEMM fp16 m16n8k16: BM=128 BN=128 BK=32, double-buffered
//    fused RMS + q-scale; V written TRANSPOSED (b,h,d,s)
// ============================================================
__global__ __launch_bounds__(256) void qkv_mma2(const float* __restrict__ rqw,
                                                const float* __restrict__ rkw) {
    __shared__ unsigned As[2][128][20];   // [m][k/2] half2, 32 halves + pad
    __shared__ unsigned Bs[2][128][20];   // [n][k/2] half2
    int tid = threadIdx.x, w = tid >> 5, lane = tid & 31, g = lane >> 2, c = lane & 3;
    int wm = w & 3, wn = w >> 2;
    int n0 = blockIdx.x * 128;
    int sel = n0 / CS, nc = n0 - sel * CS;
    const __half* Wh = g_wh[sel];
    int m0 = blockIdx.y * 128;

    float acc0[8][4] = {}, acc1[8][4] = {};
#pragma unroll
    for (int i = 0; i < 2; i++) {
        int ch = tid + 256 * i;
        int r = ch >> 2, off = ch & 3;
        cpa16(&As[0][r][off * 4], g_bsnh + (size_t)(m0 + r) * CS + off * 8);
        cpa16(&Bs[0][r][off * 4], Wh + (size_t)(nc + r) * CS + off * 8);
    }
    cp_commit(); cp_wait0();
    __syncthreads();

    int buf = 0;
    for (int it = 0; it < 24; it++) {
        if (it < 23) {
            int kn = (it + 1) * 32;
#pragma unroll
            for (int i = 0; i < 2; i++) {
                int ch = tid + 256 * i;
                int r = ch >> 2, off = ch & 3;
                cpa16(&As[buf ^ 1][r][off * 4], g_bsnh + (size_t)(m0 + r) * CS + kn + off * 8);
                cpa16(&Bs[buf ^ 1][r][off * 4], Wh + (size_t)(nc + r) * CS + kn + off * 8);
            }
            cp_commit();
        }
#pragma unroll
        for (int ks = 0; ks < 2; ks++) {
            int r0 = wm * 32 + g;
            unsigned a0[4] = {As[buf][r0][8 * ks + c], As[buf][r0 + 8][8 * ks + c],
                              As[buf][r0][8 * ks + c + 4], As[buf][r0 + 8][8 * ks + c + 4]};
            unsigned a1[4] = {As[buf][r0 + 16][8 * ks + c], As[buf][r0 + 24][8 * ks + c],
                              As[buf][r0 + 16][8 * ks + c + 4], As[buf][r0 + 24][8 * ks + c + 4]};
#pragma unroll
            for (int nt = 0; nt < 8; nt++) {
                int n = wn * 64 + 8 * nt + g;
                unsigned b0 = Bs[buf][n][8 * ks + c];
                unsigned b1 = Bs[buf][n][8 * ks + c + 4];
                mma16(acc0[nt], a0, b0, b1);
                mma16(acc1[nt], a1, b0, b1);
            }
        }
        if (it < 23) {
            cp_wait0();
            __syncthreads();
            buf ^= 1;
        }
    }

    const float SC = 0.17677669529663687f;
    int bi = m0 >> 10;
    int r0g = m0 + wm * 32 + g;
#pragma unroll
    for (int mi = 0; mi < 2; mi++) {
        float (*ac)[4] = mi ? acc1 : acc0;
        int rb = r0g + mi * 16;
        int s0 = rb & 1023, s1 = s0 + 8;
#pragma unroll
        for (int hf = 0; hf < 2; hf++) {
            int h = (nc + wn * 64 + hf * 32) >> 5;
            float ss0 = 0.f, ss1 = 0.f;
#pragma unroll
            for (int nt = hf * 4; nt < hf * 4 + 4; nt++) {
                ss0 += ac[nt][0] * ac[nt][0] + ac[nt][1] * ac[nt][1];
                ss1 += ac[nt][2] * ac[nt][2] + ac[nt][3] * ac[nt][3];
            }
            float rs0 = 1.f, rs1 = 1.f;
            if (sel < 2) {
                ss0 += __shfl_xor_sync(~0u, ss0, 1); ss0 += __shfl_xor_sync(~0u, ss0, 2);
                ss1 += __shfl_xor_sync(~0u, ss1, 1); ss1 += __shfl_xor_sync(~0u, ss1, 2);
                rs0 = rsqrtf(ss0 * (1.f / 32) + 1e-5f);
                rs1 = rsqrtf(ss1 * (1.f / 32) + 1e-5f);
                if (sel == 0) { rs0 *= SC; rs1 *= SC; }
            }
            __half* basep = g_qkvh + ((size_t)(sel * NB + bi) * NH + h) * SS * DD;
            const float* wr = (sel == 0) ? rqw : rkw;
#pragma unroll
            for (int nt = hf * 4; nt < hf * 4 + 4; nt++) {
                int d = (8 * nt + 2 * c) & 31;
                if (sel < 2) {
                    float w0 = wr[d], w1 = wr[d + 1];
                    *(unsigned*)(basep + (size_t)s0 * DD + d) =
                        pack_h2(ac[nt][0] * rs0 * w0, ac[nt][1] * rs0 * w1);
                    *(unsigned*)(basep + (size_t)s1 * DD + d) =
                        pack_h2(ac[nt][2] * rs1 * w0, ac[nt][3] * rs1 * w1);
                } else {
                    // V transposed: (d, s)
                    basep[(size_t)d * SS + s0]       = __float2half_rn(ac[nt][0]);
                    basep[(size_t)(d + 1) * SS + s0] = __float2half_rn(ac[nt][1]);
                    basep[(size_t)d * SS + s1]       = __float2half_rn(ac[nt][2]);
                    basep[(size_t)(d + 1) * SS + s1] = __float2half_rn(ac[nt][3]);
                }
            }
        }
    }
}

// ============================================================
// 4. bias via tf32 mma (R11 form, unchanged)
// ============================================================
struct BiasSmem {
    unsigned Zs[128][132];
    unsigned WT[24][132];
    float muS[128], rsS[128];
    float AhS[24], BhS[24];
    int mS[128];
};

__global__ __launch_bounds__(256) void bias_mma2(const float* __restrict__ z,
                                                 const int* __restrict__ zmask) {
    extern __shared__ char smem_raw[];
    BiasSmem* sm = (BiasSmem*)smem_raw;
    int i = blockIdx.y, jt = blockIdx.x * 128;
    int tid = threadIdx.x, w = tid >> 5, lane = tid & 31, g = lane >> 2, c = lane & 3;

    const float* zbase = z + ((size_t)i * SS + jt) * CZ;
#pragma unroll
    for (int it = 0; it < 16; it++) {
        int ch = tid + 256 * it;
        int r = ch >> 5, col = (ch & 31) * 4;
        cpa16(&sm->Zs[r][col], zbase + (size_t)r * CZ + col);
    }
    cp_commit();

    for (int idx = tid; idx < NH * CZ; idx += 256) {
        int n = idx >> 7, k = idx & 127;
        sm->WT[n][k] = g_wtp[idx];
    }
    if (tid < NH) { sm->AhS[tid] = g_ah[tid]; sm->BhS[tid] = g_bh[tid]; }
    if (tid < 128) sm->mS[tid] = zmask[(size_t)i * SS + jt + tid];
    cp_wait0();
    __syncthreads();

    {
        int r = tid >> 1, hh = tid & 1;
        const float4* zr = (const float4*)&sm->Zs[r][hh * 64];
        float s = 0.f, q = 0.f;
#pragma unroll
        for (int t = 0; t < 16; t++) {
            float4 v = zr[t];
            s += v.x + v.y + v.z + v.w;
            q += v.x * v.x + v.y * v.y + v.z * v.z + v.w * v.w;
        }
        s += __shfl_xor_sync(~0u, s, 1);
        q += __shfl_xor_sync(~0u, q, 1);
        if (hh == 0) {
            float mu = s * (1.f / CZ);
            float var = q * (1.f / CZ) - mu * mu;
            sm->muS[r] = mu;
            sm->rsS[r] = rsqrtf(var + 1e-5f);
        }
    }
    __syncthreads();

    float acc[3][4] = {};
#pragma unroll
    for (int ks = 0; ks < 16; ks++) {
        unsigned a[4] = {sm->Zs[16 * w + g][8 * ks + c], sm->Zs[16 * w + g + 8][8 * ks + c],
                         sm->Zs[16 * w + g][8 * ks + c + 4], sm->Zs[16 * w + g + 8][8 * ks + c + 4]};
#pragma unroll
        for (int nt = 0; nt < 3; nt++)
            mma8(acc[nt], a, sm->WT[8 * nt + g][8 * ks + c], sm->WT[8 * nt + g][8 * ks + c + 4]);
    }

    int j0 = 16 * w + g, j1 = j0 + 8;
    float mu0 = sm->muS[j0], rg0 = sm->rsS[j0], mu1 = sm->muS[j1], rg1 = sm->rsS[j1];
    bool k0m = sm->mS[j0] != 0, k1m = sm->mS[j1] != 0;

    __syncthreads();
    float* Ot = (float*)&sm->WT[0][0];
#pragma unroll
    for (int nt = 0; nt < 3; nt++) {
        int h = 8 * nt + 2 * c;
        float A0 = sm->AhS[h], B0 = sm->BhS[h], A1 = sm->AhS[h + 1], B1 = sm->BhS[h + 1];
        Ot[h * 132 + j0]       = k0m ? rg0 * (acc[nt][0] - mu0 * A0) + B0 : -1e9f;
        Ot[(h + 1) * 132 + j0] = k0m ? rg0 * (acc[nt][1] - mu0 * A1) + B1 : -1e9f;
        Ot[h * 132 + j1]       = k1m ? rg1 * (acc[nt][2] - mu1 * A0) + B0 : -1e9f;
        Ot[(h + 1) * 132 + j1] = k1m ? rg1 * (acc[nt][3] - mu1 * A1) + B1 : -1e9f;
    }
    __syncthreads();

    for (int idx = tid; idx < 24 * 32; idx += 256) {
        int hh = idx >> 5, j4 = (idx & 31) * 4;
        float4 v = *(float4*)&Ot[hh * 132 + j4];
        *(float4*)(g_bias + ((size_t)hh * SS + i) * SS + jt + j4) = v;
    }
}

// ============================================================
// 5. flash attention fp16 m16n8k16 (R11 running-max softmax)
//    q-tile 64, 128 thr, 4 CTA/SM; V consumed transposed
// ============================================================
struct AttnSmem {
    unsigned Qs[64][20];       // [q][d/2]
    unsigned Ks[2][64][20];    // [key][d/2]
    unsigned Vs[2][32][36];    // [d][key/2] (transposed in gmem)
    unsigned Ps[64][36];       // [q][key/2] half2
};

__global__ __launch_bounds__(128, 4) void attn_mma(const float* __restrict__ beta) {
    extern __shared__ char smem_raw[];
    AttnSmem* sm = (AttnSmem*)smem_raw;
    int b = blockIdx.z, h = blockIdx.y, q0 = blockIdx.x * 64;
    int tid = threadIdx.x, w = tid >> 5, lane = tid & 31, g = lane >> 2, c = lane & 3;

    const __half* qptr = g_qkvh + ((size_t)(0 * NB + b) * NH + h) * SS * DD;
    const __half* kptr = g_qkvh + ((size_t)(1 * NB + b) * NH + h) * SS * DD;
    const __half* vptr = g_qkvh + ((size_t)(2 * NB + b) * NH + h) * SS * DD;  // (d, s)
    const float* zbp = g_bias + ((size_t)h * SS + q0) * SS;
    const float* btp = beta + ((size_t)b * SS + q0) * SS;

    // stage Q (64x32 half) + K tile 0 + V tile 0
#pragma unroll
    for (int i = 0; i < 2; i++) {
        int ch = tid + 128 * i;                 // 0..255
        int r = ch >> 2, off = ch & 3;
        cpa16(&sm->Qs[r][off * 4], qptr + (size_t)(q0 + r) * DD + off * 8);
        cpa16(&sm->Ks[0][r][off * 4], kptr + (size_t)r * DD + off * 8);
    }
#pragma unroll
    for (int i = 0; i < 2; i++) {
        int ch = tid + 128 * i;
        int r = ch >> 3, off = ch & 7;          // 32 d-rows x 8 chunks
        cpa16(&sm->Vs[0][r][off * 4], vptr + (size_t)r * SS + off * 8);
    }
    cp_commit(); cp_wait0();
    __syncthreads();

    unsigned qa[2][4];
#pragma unroll
    for (int ks = 0; ks < 2; ks++) {
        qa[ks][0] = sm->Qs[16 * w + g][8 * ks + c];
        qa[ks][1] = sm->Qs[16 * w + g + 8][8 * ks + c];
        qa[ks][2] = sm->Qs[16 * w + g][8 * ks + c + 4];
        qa[ks][3] = sm->Qs[16 * w + g + 8][8 * ks + c + 4];
    }

    float mr0 = -1e30f, mr1 = -1e30f, l0 = 0.f, l1 = 0.f;
    float o[4][4] = {};

    int buf = 0;
    for (int kt = 0; kt < 16; kt++) {
        int k0 = kt * 64;
        if (kt < 15) {
            int kn = k0 + 64;
#pragma unroll
            for (int i = 0; i < 2; i++) {
                int ch = tid + 128 * i;
                int r = ch >> 2, off = ch & 3;
                cpa16(&sm->Ks[buf ^ 1][r][off * 4], kptr + (size_t)(kn + r) * DD + off * 8);
            }
#pragma unroll
            for (int i = 0; i < 2; i++) {
                int ch = tid + 128 * i;
                int r = ch >> 3, off = ch & 7;
                cpa16(&sm->Vs[buf ^ 1][r][off * 4], vptr + (size_t)r * SS + kn + off * 8);
            }
            cp_commit();
        }

        float s[8][4] = {};
#pragma unroll
        for (int ks = 0; ks < 2; ks++) {
#pragma unroll
            for (int nt = 0; nt < 8; nt++) {
                unsigned b0 = sm->Ks[buf][8 * nt + g][8 * ks + c];
                unsigned b1 = sm->Ks[buf][8 * nt + g][8 * ks + c + 4];
                mma16(s[nt], qa[ks], b0, b1);
            }
        }
        // bias (zbias + L2-hot beta) + running-max softmax (R11 form)
        const float* z0 = zbp + (size_t)(16 * w + g) * SS + k0 + 2 * c;
        const float* z1 = z0 + 8 * SS;
        const float* t0 = btp + (size_t)(16 * w + g) * SS + k0 + 2 * c;
        const float* t1 = t0 + 8 * SS;
        float mx0 = -1e30f, mx1 = -1e30f;
#pragma unroll
        for (int nt = 0; nt < 8; nt++) {
            float2 za = *(const float2*)(z0 + 8 * nt);
            float2 zc = *(const float2*)(z1 + 8 * nt);
            float2 ba = *(const float2*)(t0 + 8 * nt);
            float2 bc = *(const float2*)(t1 + 8 * nt);
            s[nt][0] += za.x + ba.x; s[nt][1] += za.y + ba.y;
            s[nt][2] += zc.x + bc.x; s[nt][3] += zc.y + bc.y;
            mx0 = fmaxf(mx0, fmaxf(s[nt][0], s[nt][1]));
            mx1 = fmaxf(mx1, fmaxf(s[nt][2], s[nt][3]));
        }
        mx0 = fmaxf(mx0, __shfl_xor_sync(~0u, mx0, 1));
        mx0 = fmaxf(mx0, __shfl_xor_sync(~0u, mx0, 2));
        mx1 = fmaxf(mx1, __shfl_xor_sync(~0u, mx1, 1));
        mx1 = fmaxf(mx1, __shfl_xor_sync(~0u, mx1, 2));
        float mn0 = fmaxf(mr0, mx0), mn1 = fmaxf(mr1, mx1);
        float a0 = fexp2(fmaxf((mr0 - mn0) * L2E, -126.f));
        float a1 = fexp2(fmaxf((mr1 - mn1) * L2E, -126.f));
        float m20 = mn0 * L2E, m21 = mn1 * L2E;
        float rs0 = 0.f, rs1 = 0.f;
#pragma unroll
        for (int nt = 0; nt < 8; nt++) {
            float e0 = fexp2(fmaxf(fmaf(s[nt][0], L2E, -m20), -126.f));
            float e1 = fexp2(fmaxf(fmaf(s[nt][1], L2E, -m20), -126.f));
            float e2 = fexp2(fmaxf(fmaf(s[nt][2], L2E, -m21), -126.f));
            float e3 = fexp2(fmaxf(fmaf(s[nt][3], L2E, -m21), -126.f));
            rs0 += e0 + e1; rs1 += e2 + e3;
            sm->Ps[16 * w + g][4 * nt + c]     = pack_h2(e0, e1);
            sm->Ps[16 * w + g + 8][4 * nt + c] = pack_h2(e2, e3);
        }
        rs0 += __shfl_xor_sync(~0u, rs0, 1); rs0 += __shfl_xor_sync(~0u, rs0, 2);
        rs1 += __shfl_xor_sync(~0u, rs1, 1); rs1 += __shfl_xor_sync(~0u, rs1, 2);
        l0 = l0 * a0 + rs0; l1 = l1 * a1 + rs1;
        mr0 = mn0; mr1 = mn1;
#pragma unroll
        for (int nt = 0; nt < 4; nt++) {
            o[nt][0] *= a0; o[nt][1] *= a0; o[nt][2] *= a1; o[nt][3] *= a1;
        }
        __syncwarp();
#pragma unroll
        for (int ks = 0; ks < 4; ks++) {
            unsigned pa[4] = {sm->Ps[16 * w + g][8 * ks + c],
                              sm->Ps[16 * w + g + 8][8 * ks + c],
                              sm->Ps[16 * w + g][8 * ks + c + 4],
                              sm->Ps[16 * w + g + 8][8 * ks + c + 4]};
#pragma unroll
            for (int nt = 0; nt < 4; nt++) {
                unsigned b0 = sm->Vs[buf][8 * nt + g][8 * ks + c];
                unsigned b1 = sm->Vs[buf][8 * nt + g][8 * ks + c + 4];
                mma16(o[nt], pa, b0, b1);
            }
        }
        if (kt < 15) cp_wait0();
        __syncthreads();
        buf ^= 1;
    }
    float inv0 = 1.f / l0, inv1 = 1.f / l1;
    int r0 = q0 + 16 * w + g, r1 = r0 + 8;
#pragma unroll
    for (int nt = 0; nt < 4; nt++) {
        int col = h * DD + 8 * nt + 2 * c;
        *(unsigned*)(g_atth + ((size_t)(b * SS + r0)) * CS + col) =
            pack_h2(o[nt][0] * inv0, o[nt][1] * inv0);
        *(unsigned*)(g_atth + ((size_t)(b * SS + r1)) * CS + col) =
            pack_h2(o[nt][2] * inv1, o[nt][3] * inv1);
    }
}

// ============================================================
// 6. out proj fp16 m16n8k16
// ============================================================
__global__ __launch_bounds__(256) void proj_mma2(const float* __restrict__ b_o,
                                                 float* __restrict__ out) {
    __shared__ unsigned As[2][128][20];
    __shared__ unsigned Bs[2][128][20];
    int tid = threadIdx.x, w = tid >> 5, lane = tid & 31, g = lane >> 2, c = lane & 3;
    int wm = w & 3, wn = w >> 2;
    int n0 = blockIdx.x * 128, m0 = blockIdx.y * 128;
    const __half* Wh = g_wh[3];

    float acc0[8][4] = {}, acc1[8][4] = {};
#pragma unroll
    for (int i = 0; i < 2; i++) {
        int ch = tid + 256 * i;
        int r = ch >> 2, off = ch & 3;
        cpa16(&As[0][r][off * 4], g_atth + (size_t)(m0 + r) * CS + off * 8);
        cpa16(&Bs[0][r][off * 4], Wh + (size_t)(n0 + r) * CS + off * 8);
    }
    cp_commit(); cp_wait0();
    __syncthreads();

    int buf = 0;
    for (int it = 0; it < 24; it++) {
        if (it < 23) {
            int kn = (it + 1) * 32;
#pragma unroll
            for (int i = 0; i < 2; i++) {
                int ch = tid + 256 * i;
                int r = ch >> 2, off = ch & 3;
                cpa16(&As[buf ^ 1][r][off * 4], g_atth + (size_t)(m0 + r) * CS + kn + off * 8);
                cpa16(&Bs[buf ^ 1][r][off * 4], Wh + (size_t)(n0 + r) * CS + kn + off * 8);
            }
            cp_commit();
        }
#pragma unroll
        for (int ks = 0; ks < 2; ks++) {
            int r0 = wm * 32 + g;
            unsigned a0[4] = {As[buf][r0][8 * ks + c], As[buf][r0 + 8][8 * ks + c],
                              As[buf][r0][8 * ks + c + 4], As[buf][r0 + 8][8 * ks + c + 4]};
            unsigned a1[4] = {As[buf][r0 + 16][8 * ks + c], As[buf][r0 + 24][8 * ks + c],
                              As[buf][r0 + 16][8 * ks + c + 4], As[buf][r0 + 24][8 * ks + c + 4]};
#pragma unroll
            for (int nt = 0; nt < 8; nt++) {
                int n = wn * 64 + 8 * nt + g;
                unsigned b0 = Bs[buf][n][8 * ks + c];
                unsigned b1 = Bs[buf][n][8 * ks + c + 4];
                mma16(acc0[nt], a0, b0, b1);
                mma16(acc1[nt], a1, b0, b1);
            }
        }
        if (it < 23) {
            cp_wait0();
            __syncthreads();
            buf ^= 1;
        }
    }

    int bi = m0 >> 10;
    const float* gate = g_emb + bi * 3 * CS + 2 * CS;
    int r0g = m0 + wm * 32 + g;
#pragma unroll
    for (int mi = 0; mi < 2; mi++) {
        float (*ac)[4] = mi ? acc1 : acc0;
        int rb = r0g + mi * 16;
#pragma unroll
        for (int nt = 0; nt < 8; nt++) {
            int col = n0 + wn * 64 + 8 * nt + 2 * c;
            float g0 = gate[col], g1 = gate[col + 1];
            float bo0 = b_o[col], bo1 = b_o[col + 1];
            float2 v0 = {(ac[nt][0] + bo0) * g0, (ac[nt][1] + bo1) * g1};
            *(float2*)(out + (size_t)rb * CS + col) = v0;
            float2 v1 = {(ac[nt][2] + bo0) * g0, (ac[nt][3] + bo1) * g1};
            *(float2*)(out + (size_t)(rb + 8) * CS + col) = v1;
        }
    }
}

// ============================================================
extern "C" void kernel_launch(void* const* d_in, const int* in_sizes, int n_in,
                              void* d_out, int out_size) {
    const float* bs      = (const float*)d_in[0];
    const float* z       = (const float*)d_in[1];
    const float* t       = (const float*)d_in[2];
    const float* beta    = (const float*)d_in[3];
    const int*   z_mask  = (const int*)  d_in[4];
    const float* w_adaln = (const float*)d_in[5];
    const float* b_adaln = (const float*)d_in[6];
    const float* ln_z_w  = (const float*)d_in[7];
    const float* ln_z_b  = (const float*)d_in[8];
    const float* w_q     = (const float*)d_in[9];
    const float* w_k     = (const float*)d_in[10];
    const float* w_v     = (const float*)d_in[11];
    const float* w_z     = (const float*)d_in[12];
    const float* rms_q_w = (const float*)d_in[13];
    const float* rms_k_w = (const float*)d_in[14];
    const float* w_o     = (const float*)d_in[15];
    const float* b_o     = (const float*)d_in[16];
    float* out = (float*)d_out;

    static const int ATTN_SMEM = (int)sizeof(AttnSmem);
    static const int BIAS_SMEM = (int)sizeof(BiasSmem);
    cudaFuncSetAttribute(attn_mma, cudaFuncAttributeMaxDynamicSharedMemorySize, ATTN_SMEM);
    cudaFuncSetAttribute(bias_mma2, cudaFuncAttributeMaxDynamicSharedMemorySize, BIAS_SMEM);

    adaln_kernel<<<dim3(9, 2), 256>>>(t, w_adaln, b_adaln);
    wconv_kernel<<<dim3(12, 12, 4), 256>>>(w_q, w_k, w_v, w_o);
    bprep_kernel<<<1, 256>>>(ln_z_w, ln_z_b, w_z);
    bsnorm_kernel<<<NB * SS, 256>>>(bs);
    bias_mma2<<<dim3(8, SS), 256, BIAS_SMEM>>>(z, z_mask);
    qkv_mma2<<<dim3(18, 16), 256>>>(rms_q_w, rms_k_w);
    attn_mma<<<dim3(16, NH, NB), 128, ATTN_SMEM>>>(beta);
    proj_mma2<<<dim3(6, 16), 256>>>(b_o, out);
}